// round 1
// baseline (speedup 1.0000x reference)
#include <cuda_runtime.h>
#include <cstdint>
#include <cstddef>

// Problem constants
#define B_ 512
#define T_ 1024
#define I_ 64
#define H_ 10
#define G_ 40   // 4*H

// ---------------------------------------------------------------------------
// Scratch (no cudaMalloc allowed): static __device__ global arrays.
// g_xg : input-projection output, layout [t][gate][b], padded +2 timesteps so
//        the scan's depth-2 prefetch never reads out of bounds.
// g_y1 : layer-1 hidden outputs, layout [t][j][b] (coalesced for proj2 reads).
// g_h1/g_c1 : layer-1 final state (feeds layer-2 initial state).
// ---------------------------------------------------------------------------
__device__ float g_xg[(size_t)(T_ + 2) * G_ * B_];
__device__ float g_y1[(size_t)T_ * H_ * B_];
__device__ float g_h1[B_ * H_];
__device__ float g_c1[B_ * H_];

__device__ __forceinline__ float ex2a(float x) {
    float y; asm("ex2.approx.f32 %0, %1;" : "=f"(y) : "f"(x)); return y;
}
__device__ __forceinline__ float rcpa(float x) {
    float y; asm("rcp.approx.f32 %0, %1;" : "=f"(y) : "f"(x)); return y;
}

#define L2E_ 1.4426950408889634f

// ---------------------------------------------------------------------------
// proj1: g_xg[t][g][b] = (bih[g]+bhh[g]) + sum_k x[b][t][k] * Wih[g][k]
// One thread per (b,t). b fastest within warp -> coalesced stores.
// ---------------------------------------------------------------------------
__global__ void proj1_kernel(const float* __restrict__ x,
                             const float* __restrict__ Wih,
                             const float* __restrict__ bih,
                             const float* __restrict__ bhh) {
    __shared__ __align__(16) float ws[I_ * G_];  // ws[k*G_ + g] = Wih[g][k]
    __shared__ float bs[G_];
    const int tid = threadIdx.x;
    for (int i = tid; i < I_ * G_; i += 128) {
        int k = i / G_, g = i % G_;
        ws[i] = Wih[g * I_ + k];
    }
    if (tid < G_) bs[tid] = bih[tid] + bhh[tid];
    __syncthreads();

    const int idx = blockIdx.x * 128 + tid;     // 0 .. B*T-1
    const int b = idx & (B_ - 1);
    const int t = idx >> 9;

    const float4* xp = (const float4*)(x + ((size_t)b * T_ + t) * I_);
    float acc[G_];
#pragma unroll
    for (int g = 0; g < G_; g++) acc[g] = bs[g];

    for (int k4 = 0; k4 < I_ / 4; k4++) {
        float4 xv = xp[k4];
        const float* wr = ws + k4 * 4 * G_;
#pragma unroll
        for (int kk = 0; kk < 4; kk++) {
            float xs = (kk == 0) ? xv.x : (kk == 1) ? xv.y : (kk == 2) ? xv.z : xv.w;
            const float4* wv = (const float4*)(wr + kk * G_);
#pragma unroll
            for (int g4 = 0; g4 < G_ / 4; g4++) {
                float4 wq = wv[g4];
                acc[g4 * 4 + 0] = fmaf(xs, wq.x, acc[g4 * 4 + 0]);
                acc[g4 * 4 + 1] = fmaf(xs, wq.y, acc[g4 * 4 + 1]);
                acc[g4 * 4 + 2] = fmaf(xs, wq.z, acc[g4 * 4 + 2]);
                acc[g4 * 4 + 3] = fmaf(xs, wq.w, acc[g4 * 4 + 3]);
            }
        }
    }
    float* op = g_xg + (size_t)t * (G_ * B_) + b;
#pragma unroll
    for (int g = 0; g < G_; g++) op[g * B_] = acc[g];
}

// ---------------------------------------------------------------------------
// proj2: g_xg[t][g][b] = (bih2[g]+bhh2[g]) + sum_k g_y1[t][k][b] * Wih2[g][k]
// ---------------------------------------------------------------------------
__global__ void proj2_kernel(const float* __restrict__ Wih,
                             const float* __restrict__ bih,
                             const float* __restrict__ bhh) {
    __shared__ __align__(16) float ws[H_ * G_];  // ws[k*G_ + g] = Wih[g][k]
    __shared__ float bs[G_];
    const int tid = threadIdx.x;
    for (int i = tid; i < H_ * G_; i += 128) {
        int k = i / G_, g = i % G_;
        ws[i] = Wih[g * H_ + k];
    }
    if (tid < G_) bs[tid] = bih[tid] + bhh[tid];
    __syncthreads();

    const int idx = blockIdx.x * 128 + tid;
    const int b = idx & (B_ - 1);
    const int t = idx >> 9;

    const float* yp = g_y1 + (size_t)t * (H_ * B_) + b;
    float yv[H_];
#pragma unroll
    for (int k = 0; k < H_; k++) yv[k] = yp[k * B_];

    float acc[G_];
#pragma unroll
    for (int g = 0; g < G_; g++) acc[g] = bs[g];
#pragma unroll
    for (int k = 0; k < H_; k++) {
        const float4* wv = (const float4*)(ws + k * G_);
#pragma unroll
        for (int g4 = 0; g4 < G_ / 4; g4++) {
            float4 wq = wv[g4];
            acc[g4 * 4 + 0] = fmaf(yv[k], wq.x, acc[g4 * 4 + 0]);
            acc[g4 * 4 + 1] = fmaf(yv[k], wq.y, acc[g4 * 4 + 1]);
            acc[g4 * 4 + 2] = fmaf(yv[k], wq.z, acc[g4 * 4 + 2]);
            acc[g4 * 4 + 3] = fmaf(yv[k], wq.w, acc[g4 * 4 + 3]);
        }
    }
    float* op = g_xg + (size_t)t * (G_ * B_) + b;
#pragma unroll
    for (int g = 0; g < G_; g++) op[g * B_] = acc[g];
}

// ---------------------------------------------------------------------------
// Recurrent scan. 8 lanes per batch element; lane role r in [0,8) owns gate
// rows r*5 .. r*5+4 with their Whh weights in registers. Gate type = role>>1
// (0:i, 1:f, 2:g, 3:o). After the matvec + activations, each lane gathers all
// 40 activated gate values via shfl (source lane = 2*type + (j>=5), value
// a[j%5]) and redundantly updates c/h so the next step's matvec is
// register-local in every lane.
// LAYER==1: init from h0/c0, store h to g_y1 and final state to g_h1/g_c1.
// LAYER==2: init from g_h1/g_c1, fold fc1/fc2 into a running accumulator.
// ---------------------------------------------------------------------------

#define LSTM_STEP(P, F2, TT)                                                   \
  {                                                                            \
    float val[5];                                                              \
    _Pragma("unroll") for (int j = 0; j < 5; j++) val[j] = P[j];               \
    { /* depth-2 prefetch: load t+2 into the buffer we just consumed */        \
      const float* np = xp + (size_t)((TT) + 2) * (G_ * B_);                   \
      _Pragma("unroll") for (int j = 0; j < 5; j++) P[j] = np[j * B_];         \
    }                                                                          \
    float F2n = 0.f;                                                           \
    if (LAYER == 2) F2n = ((TT) + 2 < T_) ? fc2w_p[(TT) + 2] : 0.f;            \
    _Pragma("unroll") for (int k = 0; k < H_; k++)                             \
      _Pragma("unroll") for (int j = 0; j < 5; j++)                            \
        val[j] = fmaf(w[j][k], h[k], val[j]);                                  \
    float a[5];                                                                \
    _Pragma("unroll") for (int j = 0; j < 5; j++)                              \
      a[j] = fmaf(rcpa(1.0f + ex2a(K1 * val[j])), K2, K3);                     \
    _Pragma("unroll") for (int j = 0; j < H_; j++) {                           \
      const int hi = (j >= 5) ? 1 : 0;                                         \
      float vi = __shfl_sync(0xffffffffu, a[j % 5], srcbase + 0 + hi);         \
      float vf = __shfl_sync(0xffffffffu, a[j % 5], srcbase + 2 + hi);         \
      float vg = __shfl_sync(0xffffffffu, a[j % 5], srcbase + 4 + hi);         \
      float vo = __shfl_sync(0xffffffffu, a[j % 5], srcbase + 6 + hi);         \
      c[j] = fmaf(vf, c[j], vi * vg);                                          \
      float tc = fmaf(rcpa(1.0f + ex2a(2.0f * L2E_ * c[j])), -2.0f, 1.0f);     \
      h[j] = vo * tc;                                                          \
    }                                                                          \
    if (LAYER == 1) {                                                          \
      float* yp = g_y1 + (size_t)(TT) * (H_ * B_) + b;                         \
      _Pragma("unroll") for (int j = 0; j < H_; j++) yp[j * B_] = h[j];        \
    } else {                                                                   \
      float d = f1b;                                                           \
      _Pragma("unroll") for (int j = 0; j < H_; j++)                           \
        d = fmaf(f1w[j], h[j], d);                                             \
      acc = fmaf(F2, d, acc);                                                  \
      F2 = F2n;                                                                \
    }                                                                          \
  }

template <int LAYER>
__global__ __launch_bounds__(32, 1) void scan_kernel(
    const float* __restrict__ Whh,
    const float* __restrict__ h0, const float* __restrict__ c0,
    const float* __restrict__ fc1w_p, const float* __restrict__ fc1b_p,
    const float* __restrict__ fc2w_p, const float* __restrict__ fc2b_p,
    float* __restrict__ out) {
    const int lane = threadIdx.x;
    const int role = lane & 7;
    const int bsub = lane >> 3;
    const int b = blockIdx.x * 4 + bsub;
    const int srcbase = lane & 24;  // 8-lane group base

    // Whh rows for this lane's 5 gates, kept in registers for the whole scan.
    float w[5][10];
#pragma unroll
    for (int j = 0; j < 5; j++)
#pragma unroll
        for (int k = 0; k < H_; k++)
            w[j][k] = Whh[(role * 5 + j) * H_ + k];

    // Branchless activation constants: sigmoid for types 0,1,3; tanh for 2.
    //   a = fma(rcp(1 + 2^(K1*x)), K2, K3)
    const int gtype = role >> 1;
    const float K1 = (gtype == 2) ? 2.0f * L2E_ : -L2E_;
    const float K2 = (gtype == 2) ? -2.0f : 1.0f;
    const float K3 = (gtype == 2) ? 1.0f : 0.0f;

    float h[H_], c[H_];
#pragma unroll
    for (int j = 0; j < H_; j++) {
        if (LAYER == 1) { h[j] = h0[b * H_ + j]; c[j] = c0[b * H_ + j]; }
        else            { h[j] = g_h1[b * H_ + j]; c[j] = g_c1[b * H_ + j]; }
    }

    float f1w[H_];
    float f1b = 0.f, acc = 0.f;
    if (LAYER == 2) {
#pragma unroll
        for (int j = 0; j < H_; j++) f1w[j] = fc1w_p[j];
        f1b = fc1b_p[0];
    }

    const float* xp = g_xg + (size_t)(role * 5) * B_ + b;

    // Prime the depth-2 prefetch ring.
    float p0[5], p1[5];
#pragma unroll
    for (int j = 0; j < 5; j++) {
        p0[j] = xp[j * B_];
        p1[j] = xp[(size_t)(G_ * B_) + j * B_];
    }
    float f20 = 0.f, f21 = 0.f;
    if (LAYER == 2) { f20 = fc2w_p[0]; f21 = fc2w_p[1]; }

    for (int t = 0; t < T_; t += 2) {
        LSTM_STEP(p0, f20, t)
        LSTM_STEP(p1, f21, t + 1)
    }

    if (LAYER == 1) {
        if (role == 0) {
#pragma unroll
            for (int j = 0; j < H_; j++) {
                g_h1[b * H_ + j] = h[j];
                g_c1[b * H_ + j] = c[j];
            }
        }
    } else {
        if (role == 0) out[b] = acc + fc2b_p[0];
    }
}

// ---------------------------------------------------------------------------
// Launch: proj1 -> scan layer1 -> proj2 -> scan layer2 (+ fused FC epilogue)
// ---------------------------------------------------------------------------
extern "C" void kernel_launch(void* const* d_in, const int* in_sizes, int n_in,
                              void* d_out, int out_size) {
    (void)in_sizes; (void)n_in; (void)out_size;
    const float* x    = (const float*)d_in[0];
    const float* h0   = (const float*)d_in[1];
    const float* c0   = (const float*)d_in[2];
    const float* Wih1 = (const float*)d_in[3];
    const float* Whh1 = (const float*)d_in[4];
    const float* bih1 = (const float*)d_in[5];
    const float* bhh1 = (const float*)d_in[6];
    const float* Wih2 = (const float*)d_in[7];
    const float* Whh2 = (const float*)d_in[8];
    const float* bih2 = (const float*)d_in[9];
    const float* bhh2 = (const float*)d_in[10];
    const float* fc1w = (const float*)d_in[11];
    const float* fc1b = (const float*)d_in[12];
    const float* fc2w = (const float*)d_in[13];
    const float* fc2b = (const float*)d_in[14];
    float* out = (float*)d_out;

    proj1_kernel<<<(B_ * T_) / 128, 128>>>(x, Wih1, bih1, bhh1);
    scan_kernel<1><<<B_ / 4, 32>>>(Whh1, h0, c0,
                                   nullptr, nullptr, nullptr, nullptr, nullptr);
    proj2_kernel<<<(B_ * T_) / 128, 128>>>(Wih2, bih2, bhh2);
    scan_kernel<2><<<B_ / 4, 32>>>(Whh2, nullptr, nullptr,
                                   fc1w, fc1b, fc2w, fc2b, out);
}

// round 2
// speedup vs baseline: 1.7897x; 1.7897x over previous
#include <cuda_runtime.h>
#include <cstdint>
#include <cstddef>

// Problem constants
#define B_ 512
#define T_ 1024
#define I_ 64
#define H_ 10
#define G_ 40   // 4*H

// Activation prescale constants folded into xg and Whh:
//   sigmoid(x) = rcp(1 + 2^(SI*x)),  SI = -log2(e)
//   tanh(x)    = 1 - 2*rcp(1 + 2^(SG*x)), SG = +2*log2(e)
#define SI_ (-1.4426950408889634f)
#define SG_ ( 2.8853900817779268f)

// ---------------------------------------------------------------------------
// Scratch. g_xg layout: [t][b][j][type] (type: 0=i,1=f,2=g,3=o), so that scan
// lane j reads its 4 gate pre-activations as ONE float4. Padded +8 timesteps
// for the depth-4 prefetch ring. g_y1 layout: [t][b][j].
// ---------------------------------------------------------------------------
__device__ float g_xg[(size_t)(T_ + 8) * B_ * G_];
__device__ float g_y1[(size_t)T_ * B_ * H_];
__device__ float g_h1[B_ * H_];
__device__ float g_c1[B_ * H_];

__device__ __forceinline__ float ex2a(float x) {
    float y; asm("ex2.approx.f32 %0, %1;" : "=f"(y) : "f"(x)); return y;
}
__device__ __forceinline__ float rcpa(float x) {
    float y; asm("rcp.approx.f32 %0, %1;" : "=f"(y) : "f"(x)); return y;
}

// ---------------------------------------------------------------------------
// proj1: xg(t,b,j,m) = SCALE_m * [ (bih[g]+bhh[g]) + sum_k x[b][t][k]*Wih[g][k] ]
// with g = m*10 + j. One thread per (b,t), b fastest -> coalesced-ish stores.
// ---------------------------------------------------------------------------
__global__ void proj1_kernel(const float* __restrict__ x,
                             const float* __restrict__ Wih,
                             const float* __restrict__ bih,
                             const float* __restrict__ bhh) {
    __shared__ __align__(16) float ws[I_ * G_];  // ws[k*G_ + g] = Wih[g][k]
    __shared__ float bs[G_];
    const int tid = threadIdx.x;
    for (int i = tid; i < I_ * G_; i += 128) {
        int k = i / G_, g = i % G_;
        ws[i] = Wih[g * I_ + k];
    }
    if (tid < G_) bs[tid] = bih[tid] + bhh[tid];
    __syncthreads();

    const int idx = blockIdx.x * 128 + tid;     // 0 .. B*T-1
    const int b = idx & (B_ - 1);
    const int t = idx >> 9;

    const float4* xp = (const float4*)(x + ((size_t)b * T_ + t) * I_);
    float acc[G_];
#pragma unroll
    for (int g = 0; g < G_; g++) acc[g] = bs[g];

    for (int k4 = 0; k4 < I_ / 4; k4++) {
        float4 xv = xp[k4];
        const float* wr = ws + k4 * 4 * G_;
#pragma unroll
        for (int kk = 0; kk < 4; kk++) {
            float xs = (kk == 0) ? xv.x : (kk == 1) ? xv.y : (kk == 2) ? xv.z : xv.w;
            const float4* wv = (const float4*)(wr + kk * G_);
#pragma unroll
            for (int g4 = 0; g4 < G_ / 4; g4++) {
                float4 wq = wv[g4];
                acc[g4 * 4 + 0] = fmaf(xs, wq.x, acc[g4 * 4 + 0]);
                acc[g4 * 4 + 1] = fmaf(xs, wq.y, acc[g4 * 4 + 1]);
                acc[g4 * 4 + 2] = fmaf(xs, wq.z, acc[g4 * 4 + 2]);
                acc[g4 * 4 + 3] = fmaf(xs, wq.w, acc[g4 * 4 + 3]);
            }
        }
    }
    float* op = g_xg + ((size_t)t * B_ + b) * G_;
#pragma unroll
    for (int j = 0; j < H_; j++) {
        float4 q;
        q.x = acc[j]          * SI_;   // i
        q.y = acc[H_ + j]     * SI_;   // f
        q.z = acc[2 * H_ + j] * SG_;   // g (tanh)
        q.w = acc[3 * H_ + j] * SI_;   // o
        ((float4*)op)[j] = q;
    }
}

// ---------------------------------------------------------------------------
// proj2: same, input = g_y1 ([t][b][j], contiguous 10 floats per (t,b)).
// ---------------------------------------------------------------------------
__global__ void proj2_kernel(const float* __restrict__ Wih,
                             const float* __restrict__ bih,
                             const float* __restrict__ bhh) {
    __shared__ __align__(16) float ws[H_ * G_];  // ws[k*G_ + g] = Wih[g][k]
    __shared__ float bs[G_];
    const int tid = threadIdx.x;
    for (int i = tid; i < H_ * G_; i += 128) {
        int k = i / G_, g = i % G_;
        ws[i] = Wih[g * H_ + k];
    }
    if (tid < G_) bs[tid] = bih[tid] + bhh[tid];
    __syncthreads();

    const int idx = blockIdx.x * 128 + tid;
    const int b = idx & (B_ - 1);
    const int t = idx >> 9;

    const float* yp = g_y1 + ((size_t)t * B_ + b) * H_;
    float yv[H_];
#pragma unroll
    for (int k = 0; k < H_; k++) yv[k] = yp[k];

    float acc[G_];
#pragma unroll
    for (int g = 0; g < G_; g++) acc[g] = bs[g];
#pragma unroll
    for (int k = 0; k < H_; k++) {
        const float4* wv = (const float4*)(ws + k * G_);
#pragma unroll
        for (int g4 = 0; g4 < G_ / 4; g4++) {
            float4 wq = wv[g4];
            acc[g4 * 4 + 0] = fmaf(yv[k], wq.x, acc[g4 * 4 + 0]);
            acc[g4 * 4 + 1] = fmaf(yv[k], wq.y, acc[g4 * 4 + 1]);
            acc[g4 * 4 + 2] = fmaf(yv[k], wq.z, acc[g4 * 4 + 2]);
            acc[g4 * 4 + 3] = fmaf(yv[k], wq.w, acc[g4 * 4 + 3]);
        }
    }
    float* op = g_xg + ((size_t)t * B_ + b) * G_;
#pragma unroll
    for (int j = 0; j < H_; j++) {
        float4 q;
        q.x = acc[j]          * SI_;
        q.y = acc[H_ + j]     * SI_;
        q.z = acc[2 * H_ + j] * SG_;
        q.w = acc[3 * H_ + j] * SI_;
        ((float4*)op)[j] = q;
    }
}

// ---------------------------------------------------------------------------
// Recurrent scan: 10 lanes per batch element (3 batches/warp, lanes 30,31 are
// harmless clones of lanes 20,21). Lane j owns gate rows {j,10+j,20+j,30+j}
// (one per type: i,f,g,o) with prescaled Whh rows in registers, plus state
// h[j],c[j]. After the matvec every lane has its unit's four gates LOCALLY:
// no gather shuffles, no redundant updates. Only a 10-shfl h-broadcast feeds
// the next step's matvec.
// LAYER 1: stores h to g_y1, final state to g_h1/g_c1.
// LAYER 2: folds fc1/fc2 into one local FMA per step:
//   out[b] = sum_j fc1w[j]*(sum_t fc2w[t]*h_jt) + fc1b*sum_t fc2w[t] + fc2b
// ---------------------------------------------------------------------------
template <int LAYER>
__global__ __launch_bounds__(128, 1) void scan_kernel(
    const float* __restrict__ Whh,
    const float* __restrict__ h0, const float* __restrict__ c0,
    const float* __restrict__ fc1w_p, const float* __restrict__ fc1b_p,
    const float* __restrict__ fc2w_p, const float* __restrict__ fc2b_p,
    float* __restrict__ out) {
    const int lane = threadIdx.x & 31;
    const int warp = blockIdx.x * 4 + (threadIdx.x >> 5);
    const int j    = lane % 10;                       // hidden-unit index
    const int bsub = (lane < 30) ? (lane / 10) : 2;   // clone lanes -> group 2
    const int base = bsub * 10;                       // shfl base of my group
    const int b    = warp * 3 + bsub;
    const bool active = (lane < 30) && (b < B_);
    const int bl = (b < B_) ? b : (B_ - 1);

    // Prescaled Whh rows for this lane's 4 gates (type m, unit j).
    float w[4][H_];
#pragma unroll
    for (int m = 0; m < 4; m++) {
        const float s = (m == 2) ? SG_ : SI_;
#pragma unroll
        for (int k = 0; k < H_; k++)
            w[m][k] = Whh[(m * H_ + j) * H_ + k] * s;
    }

    float h, c;
    if (LAYER == 1) { h = h0[bl * H_ + j];   c = c0[bl * H_ + j]; }
    else            { h = g_h1[bl * H_ + j]; c = g_c1[bl * H_ + j]; }

    float hk[H_];
#pragma unroll
    for (int k = 0; k < H_; k++) hk[k] = __shfl_sync(0xffffffffu, h, base + k);

    float f1wj = 0.f, accj = 0.f, sw = 0.f;
    if (LAYER == 2) f1wj = fc1w_p[j];

    // Depth-4 prefetch ring over g_xg (padded, no bounds checks needed).
    const size_t XSTR = (size_t)B_ * H_;   // float4 stride per timestep
    const float4* xp0 = (const float4*)g_xg + (size_t)bl * H_ + j;
    float4 pf[4];
#pragma unroll
    for (int d = 0; d < 4; d++) pf[d] = xp0[d * XSTR];
    const float4* xpre = xp0 + 4 * XSTR;

    float f2r[4];
    if (LAYER == 2) {
#pragma unroll
        for (int d = 0; d < 4; d++) f2r[d] = fc2w_p[d];
    }

    const size_t YSTR = (size_t)B_ * H_;   // float stride per timestep
    float* yst = g_y1 + (size_t)bl * H_ + j;

    for (int t = 0; t < T_; t += 4) {
#pragma unroll
        for (int s = 0; s < 4; s++) {
            float4 v = pf[s];
            pf[s] = xpre[0];
            xpre += XSTR;

            float vi = v.x, vf = v.y, vg = v.z, vo = v.w;
#pragma unroll
            for (int k = 0; k < H_; k++) {
                vi = fmaf(w[0][k], hk[k], vi);
                vf = fmaf(w[1][k], hk[k], vf);
                vg = fmaf(w[2][k], hk[k], vg);
                vo = fmaf(w[3][k], hk[k], vo);
            }
            // Exponent scales already folded into v and w.
            float ai = rcpa(1.0f + ex2a(vi));
            float af = rcpa(1.0f + ex2a(vf));
            float ag = fmaf(rcpa(1.0f + ex2a(vg)), -2.0f, 1.0f);
            float ao = rcpa(1.0f + ex2a(vo));

            c = fmaf(af, c, ai * ag);
            float tc = fmaf(rcpa(1.0f + ex2a(SG_ * c)), -2.0f, 1.0f);
            h = ao * tc;

#pragma unroll
            for (int k = 0; k < H_; k++)
                hk[k] = __shfl_sync(0xffffffffu, h, base + k);

            if (LAYER == 1) {
                if (active) yst[0] = h;
                yst += YSTR;
            } else {
                float f2c = f2r[s];
                int nt = t + s + 4;
                f2r[s] = (nt < T_) ? fc2w_p[nt] : 0.f;
                accj = fmaf(f2c, h, accj);
                sw += f2c;
            }
        }
    }

    if (LAYER == 1) {
        if (active) {
            g_h1[b * H_ + j] = h;
            g_c1[b * H_ + j] = c;
        }
    } else {
        float part = f1wj * accj;
        float sum = part;
#pragma unroll
        for (int k = 1; k < H_; k++)
            sum += __shfl_sync(0xffffffffu, part, base + k);
        if (active && j == 0)
            out[b] = sum + fc1b_p[0] * sw + fc2b_p[0];
    }
}

// ---------------------------------------------------------------------------
// Launch: proj1 -> scan1 -> proj2 -> scan2 (+ fused FC epilogue).
// 172 warps (ceil(512/3)) in 43 blocks x 128 threads: all co-resident.
// ---------------------------------------------------------------------------
extern "C" void kernel_launch(void* const* d_in, const int* in_sizes, int n_in,
                              void* d_out, int out_size) {
    (void)in_sizes; (void)n_in; (void)out_size;
    const float* x    = (const float*)d_in[0];
    const float* h0   = (const float*)d_in[1];
    const float* c0   = (const float*)d_in[2];
    const float* Wih1 = (const float*)d_in[3];
    const float* Whh1 = (const float*)d_in[4];
    const float* bih1 = (const float*)d_in[5];
    const float* bhh1 = (const float*)d_in[6];
    const float* Wih2 = (const float*)d_in[7];
    const float* Whh2 = (const float*)d_in[8];
    const float* bih2 = (const float*)d_in[9];
    const float* bhh2 = (const float*)d_in[10];
    const float* fc1w = (const float*)d_in[11];
    const float* fc1b = (const float*)d_in[12];
    const float* fc2w = (const float*)d_in[13];
    const float* fc2b = (const float*)d_in[14];
    float* out = (float*)d_out;

    proj1_kernel<<<(B_ * T_) / 128, 128>>>(x, Wih1, bih1, bhh1);
    scan_kernel<1><<<43, 128>>>(Whh1, h0, c0,
                                nullptr, nullptr, nullptr, nullptr, nullptr);
    proj2_kernel<<<(B_ * T_) / 128, 128>>>(Wih2, bih2, bhh2);
    scan_kernel<2><<<43, 128>>>(Whh2, nullptr, nullptr,
                                fc1w, fc1b, fc2w, fc2b, out);
}